// round 17
// baseline (speedup 1.0000x reference)
#include <cuda_runtime.h>
#include <cuda_bf16.h>
#include <cstdint>

// CrossAttentionFusion: B=4, S2_CH=256, DEM_CH=64, OUT_CH=256, H=W=64, N=4096
#define BB 4
#define CS 256
#define CD 64
#define CO 256
#define NN 4096
#define SCALE 0.0625f
#define NJB 32
#define NPART (NJB * 4)        // 128 partials per (b, i)

// Scratch (device globals: allocation-free rule)
__device__ __nv_bfloat16 g_Xs[(size_t)BB * CS * NN];   // x_s2 bf16 [b][c][n]
__device__ __nv_bfloat16 g_Xd[(size_t)BB * CD * NN];   // x_dem bf16 [b][c][n]
__device__ __nv_bfloat16 g_Wq[(size_t)CO * CS];        // Wq bf16
__device__ __nv_bfloat16 g_Wk[(size_t)CO * CD];        // Wk bf16
__device__ __nv_bfloat16 g_Wv[(size_t)CO * CD];        // Wv bf16
__device__ __nv_bfloat16 g_Qt[(size_t)BB * NN * CO];   // Q^T bf16 [b][j][c] (scale folded)
__device__ __nv_bfloat16 g_Kt[(size_t)BB * NN * CO];   // K^T bf16 [b][i][c]
__device__ __nv_bfloat16 g_Vr[(size_t)BB * CO * NN];   // V bf16 [b][c][i] (unscaled)
__device__ __nv_bfloat16 g_Vb[(size_t)BB * CO * NN];   // V' = V/R bf16 [b][c][i]
__device__ __nv_bfloat16 g_E [(size_t)BB * NN * NN];   // exp(logits) bf16 [b][i][j]
__device__ float         g_Rp[(size_t)BB * NPART * NN];// row-sum partials
__device__ float         g_R [(size_t)BB * NN];        // row sums of E

// ===========================================================================
// helpers
// ===========================================================================
__device__ __forceinline__ uint32_t smem_u32(const void* p) {
    uint32_t a;
    asm("{ .reg .u64 t; cvta.to.shared.u64 t, %1; cvt.u32.u64 %0, t; }"
        : "=r"(a) : "l"(p));
    return a;
}

#define CP16(dst, src) \
    asm volatile("cp.async.cg.shared.global [%0], [%1], 16;" \
                 :: "r"(dst), "l"(src))
#define CP_COMMIT() asm volatile("cp.async.commit_group;" ::: "memory")
#define CP_WAITN(n) asm volatile("cp.async.wait_group %0;" :: "n"(n) : "memory")

#define LDSM2T(r0, r1, addr) \
    asm volatile("ldmatrix.sync.aligned.m8n8.x2.trans.shared.b16 {%0,%1}, [%2];" \
                 : "=r"(r0), "=r"(r1) : "r"(addr))

#define MMA_BF16(d, av, bv) \
    asm volatile("mma.sync.aligned.m16n8k16.row.col.f32.bf16.bf16.f32 " \
                 "{%0,%1,%2,%3}, {%4,%5,%6,%7}, {%8,%9}, {%0,%1,%2,%3};" \
                 : "+f"((d)[0]), "+f"((d)[1]), "+f"((d)[2]), "+f"((d)[3]) \
                 : "r"((av)[0]), "r"((av)[1]), "r"((av)[2]), "r"((av)[3]), \
                   "r"((bv)[0]), "r"((bv)[1]))

__device__ __forceinline__ uint2 pack4bf(float a, float b, float c, float d) {
    __nv_bfloat162 lo = __floats2bfloat162_rn(a, b);
    __nv_bfloat162 hi = __floats2bfloat162_rn(c, d);
    uint2 r;
    r.x = *(uint32_t*)&lo;
    r.y = *(uint32_t*)&hi;
    return r;
}

#define SA_STRIDE 80                       // 32 bf16 (64B) + 16B pad
#define SA_BYTES  (128 * SA_STRIDE)        // 10240
#define SBO_STRIDE 272                     // 128 bf16 (256B) + 16B pad
#define SBO_BYTES  (32 * SBO_STRIDE)       // 8704
#define P_STAGE   (SA_BYTES + SBO_BYTES)   // 18944

// ===========================================================================
// cvt: bf16(X) elementwise, 4 per thread
// ===========================================================================
__global__ void cvt_bf16_kernel(const float* __restrict__ X,
                                __nv_bfloat16* __restrict__ Y)
{
    size_t i = ((size_t)blockIdx.x * 256 + threadIdx.x) * 4;
    float4 v = *(const float4*)&X[i];
    *(uint2*)&Y[i] = pack4bf(v.x, v.y, v.z, v.w);
}

// ===========================================================================
// projT_mma: Yt[b,j,c] = ( sum_k X[b,k,j] * W[c,k] + bias[c] ) * scale
// ===========================================================================
template <int CIN>
__global__ void __launch_bounds__(256, 1)
projT_mma(const __nv_bfloat16* __restrict__ X,
          const __nv_bfloat16* __restrict__ Wb,
          const float* __restrict__ bias,
          __nv_bfloat16* __restrict__ Yt, float scale)
{
    constexpr int NCH = CIN / 32;
    __shared__ __align__(16) char sm[2 * P_STAGE];
    const int tid = threadIdx.x, lane = tid & 31, wid = tid >> 5;
    const int b = blockIdx.z, j0 = blockIdx.x * 128, c0 = blockIdx.y * 128;
    const int wm = wid & 1, wn = wid >> 1;
    const int qr = lane >> 2;
    const int qk = (lane & 3) * 2;

    const __nv_bfloat16* Xb = X + (size_t)b * CIN * NN;
    const uint32_t sbase = smem_u32(sm);

    const int crow = tid >> 2, cseg = tid & 3;
    const int brow = tid >> 4, bseg = tid & 15;

    auto issue = [&](int ch, int st) {
        uint32_t sW = sbase + st * P_STAGE;
        uint32_t sX = sW + SA_BYTES;
        const int k0 = ch * 32;
        #pragma unroll
        for (int t = 0; t < 2; t++) {
            int rw = crow + t * 64;
            CP16(sW + (uint32_t)(rw * SA_STRIDE + cseg * 16),
                 Wb + (size_t)(c0 + rw) * CIN + k0 + cseg * 8);
            int rx = brow + t * 16;
            CP16(sX + (uint32_t)(rx * SBO_STRIDE + bseg * 16),
                 Xb + (size_t)(k0 + rx) * NN + j0 + bseg * 8);
        }
        CP_COMMIT();
    };

    float acc[4][4][4] = {};
    issue(0, 0);
    issue(1, 1);

    #pragma unroll 1
    for (int ch = 0; ch < NCH; ch++) {
        const int st = ch & 1;
        if (ch == NCH - 1) CP_WAITN(0); else CP_WAITN(1);
        __syncthreads();
        const char* pW = sm + st * P_STAGE;
        const char* pX = pW + SA_BYTES;
        #pragma unroll
        for (int ks = 0; ks < 2; ks++) {
            const int kbyte = qk * 2 + ks * 32;
            uint32_t a[4][4], bb[4][2];
            #pragma unroll
            for (int mf = 0; mf < 4; mf++) {
                int j = wm * 64 + mf * 16 + qr;
                const char* colp = pX + (size_t)(ks * 16 + qk) * SBO_STRIDE + j * 2;
                uint32_t p0 = *(const uint16_t*)(colp);
                uint32_t p1 = *(const uint16_t*)(colp + SBO_STRIDE);
                uint32_t p2 = *(const uint16_t*)(colp + 16);
                uint32_t p3 = *(const uint16_t*)(colp + SBO_STRIDE + 16);
                uint32_t p4 = *(const uint16_t*)(colp + 8 * SBO_STRIDE);
                uint32_t p5 = *(const uint16_t*)(colp + 9 * SBO_STRIDE);
                uint32_t p6 = *(const uint16_t*)(colp + 8 * SBO_STRIDE + 16);
                uint32_t p7 = *(const uint16_t*)(colp + 9 * SBO_STRIDE + 16);
                a[mf][0] = p0 | (p1 << 16);
                a[mf][1] = p2 | (p3 << 16);
                a[mf][2] = p4 | (p5 << 16);
                a[mf][3] = p6 | (p7 << 16);
            }
            #pragma unroll
            for (int nf = 0; nf < 4; nf++) {
                int n = wn * 32 + nf * 8 + qr;
                const char* base = pW + n * SA_STRIDE + kbyte;
                bb[nf][0] = *(const uint32_t*)(base);
                bb[nf][1] = *(const uint32_t*)(base + 16);
            }
            #pragma unroll
            for (int mf = 0; mf < 4; mf++)
                #pragma unroll
                for (int nf = 0; nf < 4; nf++)
                    MMA_BF16(acc[mf][nf], a[mf], bb[nf]);
        }
        __syncthreads();
        if (ch + 2 < NCH) issue(ch + 2, st);
    }

    const int qc = (lane & 3) * 2;
    __nv_bfloat16* Yb = Yt + ((size_t)b * NN + j0) * CO + c0;
    #pragma unroll
    for (int mf = 0; mf < 4; mf++) {
        #pragma unroll
        for (int nf = 0; nf < 4; nf++) {
            int r = wm * 64 + mf * 16 + qr;
            int c = wn * 32 + nf * 8 + qc;
            float b0 = bias[c0 + c], b1 = bias[c0 + c + 1];
            *(__nv_bfloat162*)&Yb[(size_t)r * CO + c] =
                __floats2bfloat162_rn((acc[mf][nf][0] + b0) * scale,
                                      (acc[mf][nf][1] + b1) * scale);
            *(__nv_bfloat162*)&Yb[(size_t)(r + 8) * CO + c] =
                __floats2bfloat162_rn((acc[mf][nf][2] + b0) * scale,
                                      (acc[mf][nf][3] + b1) * scale);
        }
    }
}

// ===========================================================================
// projN_mma: Y[b,c,i] = sum_k W[c,k] * X[b,k,i] + bias[c]
// ===========================================================================
template <int CIN>
__global__ void __launch_bounds__(256, 1)
projN_mma(const __nv_bfloat16* __restrict__ X,
          const __nv_bfloat16* __restrict__ Wb,
          const float* __restrict__ bias,
          __nv_bfloat16* __restrict__ Y)
{
    constexpr int NCH = CIN / 32;
    __shared__ __align__(16) char sm[2 * P_STAGE];
    const int tid = threadIdx.x, lane = tid & 31, wid = tid >> 5;
    const int b = blockIdx.z, i0 = blockIdx.x * 128, c0 = blockIdx.y * 128;
    const int wm = wid & 1, wn = wid >> 1;
    const int qr = lane >> 2;
    const int qk = (lane & 3) * 2;

    const __nv_bfloat16* Xb = X + (size_t)b * CIN * NN;
    const uint32_t sbase = smem_u32(sm);

    const int crow = tid >> 2, cseg = tid & 3;
    const int brow = tid >> 4, bseg = tid & 15;

    auto issue = [&](int ch, int st) {
        uint32_t sW = sbase + st * P_STAGE;
        uint32_t sX = sW + SA_BYTES;
        const int k0 = ch * 32;
        #pragma unroll
        for (int t = 0; t < 2; t++) {
            int rw = crow + t * 64;
            CP16(sW + (uint32_t)(rw * SA_STRIDE + cseg * 16),
                 Wb + (size_t)(c0 + rw) * CIN + k0 + cseg * 8);
            int rx = brow + t * 16;
            CP16(sX + (uint32_t)(rx * SBO_STRIDE + bseg * 16),
                 Xb + (size_t)(k0 + rx) * NN + i0 + bseg * 8);
        }
        CP_COMMIT();
    };

    float acc[4][4][4] = {};
    issue(0, 0);
    issue(1, 1);

    #pragma unroll 1
    for (int ch = 0; ch < NCH; ch++) {
        const int st = ch & 1;
        if (ch == NCH - 1) CP_WAITN(0); else CP_WAITN(1);
        __syncthreads();
        const char* pW = sm + st * P_STAGE;
        const char* pX = pW + SA_BYTES;
        #pragma unroll
        for (int ks = 0; ks < 2; ks++) {
            const int kbyte = qk * 2 + ks * 32;
            uint32_t a[4][4], bb[4][2];
            #pragma unroll
            for (int mf = 0; mf < 4; mf++) {
                int r = wm * 64 + mf * 16 + qr;
                const char* base = pW + r * SA_STRIDE + kbyte;
                a[mf][0] = *(const uint32_t*)(base);
                a[mf][1] = *(const uint32_t*)(base + 8 * SA_STRIDE);
                a[mf][2] = *(const uint32_t*)(base + 16);
                a[mf][3] = *(const uint32_t*)(base + 8 * SA_STRIDE + 16);
            }
            #pragma unroll
            for (int nf = 0; nf < 4; nf++) {
                int n = wn * 32 + nf * 8 + qr;
                const char* colp = pX + (size_t)(ks * 16 + qk) * SBO_STRIDE + n * 2;
                uint32_t p0 = *(const uint16_t*)(colp);
                uint32_t p1 = *(const uint16_t*)(colp + SBO_STRIDE);
                uint32_t p2 = *(const uint16_t*)(colp + 8 * SBO_STRIDE);
                uint32_t p3 = *(const uint16_t*)(colp + 9 * SBO_STRIDE);
                bb[nf][0] = p0 | (p1 << 16);
                bb[nf][1] = p2 | (p3 << 16);
            }
            #pragma unroll
            for (int mf = 0; mf < 4; mf++)
                #pragma unroll
                for (int nf = 0; nf < 4; nf++)
                    MMA_BF16(acc[mf][nf], a[mf], bb[nf]);
        }
        __syncthreads();
        if (ch + 2 < NCH) issue(ch + 2, st);
    }

    const int qc = (lane & 3) * 2;
    __nv_bfloat16* Yb = Y + ((size_t)b * CO + c0) * NN + i0;
    #pragma unroll
    for (int mf = 0; mf < 4; mf++) {
        #pragma unroll
        for (int nf = 0; nf < 4; nf++) {
            int r = wm * 64 + mf * 16 + qr;
            int c = wn * 32 + nf * 8 + qc;
            float br0 = bias[c0 + r], br8 = bias[c0 + r + 8];
            *(__nv_bfloat162*)&Yb[(size_t)r * NN + c] =
                __floats2bfloat162_rn(acc[mf][nf][0] + br0, acc[mf][nf][1] + br0);
            *(__nv_bfloat162*)&Yb[(size_t)(r + 8) * NN + c] =
                __floats2bfloat162_rn(acc[mf][nf][2] + br8, acc[mf][nf][3] + br8);
        }
    }
}

// ===========================================================================
// s_mma_d: E[b,i,j] = exp( sum_c Kt[b,i,c] * Qt[b,j,c] )   (scale in Qt)
// Epilogue emits lightweight per-warp row-sum partials (no smem, no barriers):
// Rp[((b*NJB+jblk)*4+wn)][i] = sum of this warp's 32-j slice of row i.
// ===========================================================================
#define S_STAGE   (2 * SA_BYTES)

__global__ void __launch_bounds__(256, 1)
s_mma_d(const __nv_bfloat16* __restrict__ Kt,
        const __nv_bfloat16* __restrict__ Qt,
        __nv_bfloat16* __restrict__ E,
        float* __restrict__ Rp)
{
    __shared__ __align__(16) char sm[2 * S_STAGE];   // 40 KB
    const int tid = threadIdx.x, lane = tid & 31, wid = tid >> 5;
    const int b = blockIdx.z, i0 = blockIdx.y * 128, j0 = blockIdx.x * 128;
    const int jblk = blockIdx.x;
    const int wm = wid & 1, wn = wid >> 1;
    const int qr = lane >> 2;
    const int qk = (lane & 3) * 2;

    const __nv_bfloat16* Ag = Kt + ((size_t)b * NN + i0) * CS;
    const __nv_bfloat16* Bg = Qt + ((size_t)b * NN + j0) * CS;
    const uint32_t sbase = smem_u32(sm);

    const int crow = tid >> 2, cseg = tid & 3;

    auto issue = [&](int ch, int st) {
        uint32_t sA = sbase + st * S_STAGE;
        uint32_t sB = sA + SA_BYTES;
        const __nv_bfloat16* a0 = Ag + ch * 32;
        const __nv_bfloat16* b0 = Bg + ch * 32;
        #pragma unroll
        for (int t = 0; t < 2; t++) {
            int row = crow + t * 64;
            uint32_t off = (uint32_t)(row * SA_STRIDE + cseg * 16);
            CP16(sA + off, a0 + (size_t)row * CS + cseg * 8);
            CP16(sB + off, b0 + (size_t)row * CS + cseg * 8);
        }
        CP_COMMIT();
    };

    float acc[4][4][4] = {};
    issue(0, 0);
    issue(1, 1);

    #pragma unroll 1
    for (int ch = 0; ch < 8; ch++) {
        const int st = ch & 1;
        if (ch == 7) CP_WAITN(0); else CP_WAITN(1);
        __syncthreads();
        const char* pA = sm + st * S_STAGE;
        const char* pB = pA + SA_BYTES;
        #pragma unroll
        for (int ks = 0; ks < 2; ks++) {
            const int kbyte = ks * 32 + qk * 2;
            uint32_t a[4][4], bb[4][2];
            #pragma unroll
            for (int mf = 0; mf < 4; mf++) {
                int r = wm * 64 + mf * 16 + qr;
                const char* base = pA + r * SA_STRIDE + kbyte;
                a[mf][0] = *(const uint32_t*)(base);
                a[mf][1] = *(const uint32_t*)(base + 8 * SA_STRIDE);
                a[mf][2] = *(const uint32_t*)(base + 16);
                a[mf][3] = *(const uint32_t*)(base + 8 * SA_STRIDE + 16);
            }
            #pragma unroll
            for (int nf = 0; nf < 4; nf++) {
                int n = wn * 32 + nf * 8 + qr;
                const char* base = pB + n * SA_STRIDE + kbyte;
                bb[nf][0] = *(const uint32_t*)(base);
                bb[nf][1] = *(const uint32_t*)(base + 16);
            }
            #pragma unroll
            for (int mf = 0; mf < 4; mf++)
                #pragma unroll
                for (int nf = 0; nf < 4; nf++)
                    MMA_BF16(acc[mf][nf], a[mf], bb[nf]);
        }
        __syncthreads();
        if (ch + 2 < 8) issue(ch + 2, st);
    }

    const int qc = (lane & 3) * 2;
    __nv_bfloat16* Eb = E + ((size_t)b * NN + i0) * NN + j0;
    float* Rpw = Rp + ((size_t)((b * NJB + jblk) * 4) + wn) * NN + i0;
    #pragma unroll
    for (int mf = 0; mf < 4; mf++) {
        float s0 = 0.0f, s1 = 0.0f;
        #pragma unroll
        for (int nf = 0; nf < 4; nf++) {
            int r = wm * 64 + mf * 16 + qr;
            int c = wn * 32 + nf * 8 + qc;
            __nv_bfloat162 h0 = __floats2bfloat162_rn(__expf(acc[mf][nf][0]),
                                                      __expf(acc[mf][nf][1]));
            __nv_bfloat162 h1 = __floats2bfloat162_rn(__expf(acc[mf][nf][2]),
                                                      __expf(acc[mf][nf][3]));
            *(__nv_bfloat162*)&Eb[(size_t)r * NN + c] = h0;
            *(__nv_bfloat162*)&Eb[(size_t)(r + 8) * NN + c] = h1;
            float2 f0 = __bfloat1622float2(h0);
            float2 f1 = __bfloat1622float2(h1);
            s0 += f0.x + f0.y;
            s1 += f1.x + f1.y;
        }
        s0 += __shfl_xor_sync(0xFFFFFFFFu, s0, 1);
        s0 += __shfl_xor_sync(0xFFFFFFFFu, s0, 2);
        s1 += __shfl_xor_sync(0xFFFFFFFFu, s1, 1);
        s1 += __shfl_xor_sync(0xFFFFFFFFu, s1, 2);
        if ((lane & 3) == 0) {
            int r = wm * 64 + mf * 16 + qr;
            Rpw[r] = s0;
            Rpw[r + 8] = s1;
        }
    }
}

// ===========================================================================
// rp_reduce: R[b,i] = sum_p Rp[b*NPART+p][i]   (coalesced over i)
// ===========================================================================
__global__ void rp_reduce_kernel(const float* __restrict__ Rp,
                                 float* __restrict__ R)
{
    const int b = blockIdx.y;
    const int i = blockIdx.x * 256 + threadIdx.x;
    const float* base = Rp + (size_t)b * NPART * NN + i;
    float s = 0.0f;
    #pragma unroll 8
    for (int p = 0; p < NPART; p++)
        s += base[(size_t)p * NN];
    R[(size_t)b * NN + i] = s;
}

// ===========================================================================
// vscale: Vb[b,c,i] = bf16( f32(Vr[b,c,i]) / R[b,i] )
// ===========================================================================
__global__ void vscale_kernel(const __nv_bfloat16* __restrict__ Vr,
                              const float* __restrict__ R,
                              __nv_bfloat16* __restrict__ Vb)
{
    size_t idx = ((size_t)blockIdx.x * 256 + threadIdx.x) * 8;
    int i = (int)(idx & (NN - 1));
    int b = (int)(idx >> 20);                 // CO*NN = 2^20
    uint4 v = *(const uint4*)&Vr[idx];
    float4 r0 = *(const float4*)&R[(size_t)b * NN + i];
    float4 r1 = *(const float4*)&R[(size_t)b * NN + i + 4];
    float2 f0 = __bfloat1622float2(*(const __nv_bfloat162*)&v.x);
    float2 f1 = __bfloat1622float2(*(const __nv_bfloat162*)&v.y);
    float2 f2 = __bfloat1622float2(*(const __nv_bfloat162*)&v.z);
    float2 f3 = __bfloat1622float2(*(const __nv_bfloat162*)&v.w);
    uint2 o0 = pack4bf(f0.x / r0.x, f0.y / r0.y, f1.x / r0.z, f1.y / r0.w);
    uint2 o1 = pack4bf(f2.x / r1.x, f2.y / r1.y, f3.x / r1.z, f3.y / r1.w);
    uint4 o = make_uint4(o0.x, o0.y, o1.x, o1.y);
    *(uint4*)&Vb[idx] = o;
}

// ===========================================================================
// out_mma_d: out[b,c,j] = sum_i V'[b,c,i]*E[b,i,j] + xs2
// 3-stage cp.async pipeline (R12-proven).
// ===========================================================================
#define O_STAGE    (SA_BYTES + SBO_BYTES)  // 18944
#define O_NSTAGE   3
#define O_SMEM     (O_NSTAGE * O_STAGE)    // 56832

__global__ void __launch_bounds__(256, 1)
out_mma_d(const __nv_bfloat16* __restrict__ V,
          const __nv_bfloat16* __restrict__ E,
          const float* __restrict__ xs2,
          float* __restrict__ out)
{
    extern __shared__ __align__(16) char sm[];
    const int tid = threadIdx.x, lane = tid & 31, wid = tid >> 5;
    const int b = blockIdx.z, c0 = blockIdx.y * 128, j0 = blockIdx.x * 128;
    const int wm = wid & 1, wn = wid >> 1;
    const int qr = lane >> 2;
    const int qk = (lane & 3) * 2;
    const int ln = lane & 15;

    const __nv_bfloat16* Ag = V + ((size_t)b * CO + c0) * NN;
    const __nv_bfloat16* Bg = E + (size_t)b * NN * NN + j0;
    const uint32_t sbase = smem_u32(sm);

    const int arow = tid >> 2, aseg = tid & 3;
    const int brow = tid >> 4, bseg = tid & 15;

    auto issue = [&](int ch, int st) {
        uint32_t sA = sbase + st * O_STAGE;
        uint32_t sB = sA + SA_BYTES;
        const __nv_bfloat16* a0 = Ag + ch * 32;
        const __nv_bfloat16* b0 = Bg + (size_t)(ch * 32) * NN;
        #pragma unroll
        for (int t = 0; t < 2; t++) {
            int ra = arow + t * 64;
            CP16(sA + (uint32_t)(ra * SA_STRIDE + aseg * 16),
                 a0 + (size_t)ra * NN + aseg * 8);
            int rb = brow + t * 16;
            CP16(sB + (uint32_t)(rb * SBO_STRIDE + bseg * 16),
                 b0 + (size_t)rb * NN + bseg * 8);
        }
        CP_COMMIT();
    };

    float acc[4][4][4] = {};
    issue(0, 0);
    issue(1, 1);
    issue(2, 2);

    const int NCH = NN / 32;   // 128
    int st = 0;
    #pragma unroll 1
    for (int ch = 0; ch < NCH; ch++) {
        if (ch < NCH - 2)       CP_WAITN(2);
        else if (ch == NCH - 2) CP_WAITN(1);
        else                    CP_WAITN(0);
        __syncthreads();
        const char* pA = sm + st * O_STAGE;
        const uint32_t sB32 = sbase + st * O_STAGE + SA_BYTES;
        #pragma unroll
        for (int ks = 0; ks < 2; ks++) {
            const int kbyteA = ks * 32 + qk * 2;
            const uint32_t brow_addr = sB32 + (uint32_t)((ks * 16 + ln) * SBO_STRIDE
                                                         + wn * 64);
            uint32_t a[4][4], bb[4][2];
            #pragma unroll
            for (int mf = 0; mf < 4; mf++) {
                int r = wm * 64 + mf * 16 + qr;
                const char* base = pA + r * SA_STRIDE + kbyteA;
                a[mf][0] = *(const uint32_t*)(base);
                a[mf][1] = *(const uint32_t*)(base + 8 * SA_STRIDE);
                a[mf][2] = *(const uint32_t*)(base + 16);
                a[mf][3] = *(const uint32_t*)(base + 8 * SA_STRIDE + 16);
            }
            #pragma unroll
            for (int nf = 0; nf < 4; nf++)
                LDSM2T(bb[nf][0], bb[nf][1], brow_addr + nf * 16);
            #pragma unroll
            for (int mf = 0; mf < 4; mf++)
                #pragma unroll
                for (int nf = 0; nf < 4; nf++)
                    MMA_BF16(acc[mf][nf], a[mf], bb[nf]);
        }
        __syncthreads();
        if (ch + 3 < NCH) issue(ch + 3, st);
        st = (st == O_NSTAGE - 1) ? 0 : st + 1;
    }

    const int qc = (lane & 3) * 2;
    const float* Xb = xs2 + ((size_t)b * CO + c0) * NN + j0;
    float* Ob = out + ((size_t)b * CO + c0) * NN + j0;
    #pragma unroll
    for (int mf = 0; mf < 4; mf++) {
        #pragma unroll
        for (int nf = 0; nf < 4; nf++) {
            int r = wm * 64 + mf * 16 + qr;
            int c = wn * 32 + nf * 8 + qc;
            float2 x0 = *(const float2*)&Xb[(size_t)r * NN + c];
            float2 x1 = *(const float2*)&Xb[(size_t)(r + 8) * NN + c];
            *(float2*)&Ob[(size_t)r * NN + c] =
                make_float2(acc[mf][nf][0] + x0.x, acc[mf][nf][1] + x0.y);
            *(float2*)&Ob[(size_t)(r + 8) * NN + c] =
                make_float2(acc[mf][nf][2] + x1.x, acc[mf][nf][3] + x1.y);
        }
    }
}

// ===========================================================================
extern "C" void kernel_launch(void* const* d_in, const int* in_sizes, int n_in,
                              void* d_out, int out_size)
{
    const float* x_s2  = (const float*)d_in[0];
    const float* x_dem = (const float*)d_in[1];
    const float* Wq    = (const float*)d_in[2];
    const float* bq    = (const float*)d_in[3];
    const float* Wk    = (const float*)d_in[4];
    const float* bk    = (const float*)d_in[5];
    const float* Wv    = (const float*)d_in[6];
    const float* bv    = (const float*)d_in[7];
    float* out = (float*)d_out;

    float *Rpp, *Rsum;
    __nv_bfloat16 *Xs, *Xd, *Wqb, *Wkb, *Wvb, *Qt, *Kt, *Vr, *Vb, *Ep;
    cudaGetSymbolAddress((void**)&Xs, g_Xs);
    cudaGetSymbolAddress((void**)&Xd, g_Xd);
    cudaGetSymbolAddress((void**)&Wqb, g_Wq);
    cudaGetSymbolAddress((void**)&Wkb, g_Wk);
    cudaGetSymbolAddress((void**)&Wvb, g_Wv);
    cudaGetSymbolAddress((void**)&Qt, g_Qt);
    cudaGetSymbolAddress((void**)&Kt, g_Kt);
    cudaGetSymbolAddress((void**)&Vr, g_Vr);
    cudaGetSymbolAddress((void**)&Vb, g_Vb);
    cudaGetSymbolAddress((void**)&Ep, g_E);
    cudaGetSymbolAddress((void**)&Rpp, g_Rp);
    cudaGetSymbolAddress((void**)&Rsum, g_R);

    cudaFuncSetAttribute(out_mma_d, cudaFuncAttributeMaxDynamicSharedMemorySize, O_SMEM);

    // One-time host-side stream/event setup (no device memory involved).
    static cudaStream_t s1 = nullptr, s2 = nullptr;
    static cudaEvent_t evRoot = nullptr, evXd = nullptr, evK = nullptr, evV = nullptr;
    if (!s1) {
        cudaStreamCreateWithFlags(&s1, cudaStreamNonBlocking);
        cudaStreamCreateWithFlags(&s2, cudaStreamNonBlocking);
        cudaEventCreateWithFlags(&evRoot, cudaEventDisableTiming);
        cudaEventCreateWithFlags(&evXd, cudaEventDisableTiming);
        cudaEventCreateWithFlags(&evK, cudaEventDisableTiming);
        cudaEventCreateWithFlags(&evV, cudaEventDisableTiming);
    }

    dim3 blk(256);
    dim3 grid_pt(NN / 128, CO / 128, BB);     // (32, 2, 4)

    // Fork from the (capturing) default stream.
    cudaEventRecord(evRoot, 0);
    cudaStreamWaitEvent(s1, evRoot, 0);
    cudaStreamWaitEvent(s2, evRoot, 0);

    // Branch s1: x_dem cvt, Wk cvt, K projection (transposed output)
    cvt_bf16_kernel<<<(unsigned)((size_t)BB * CD * NN / 1024), 256, 0, s1>>>(x_dem, Xd);
    cudaEventRecord(evXd, s1);
    cvt_bf16_kernel<<<CO * CD / 1024, 256, 0, s1>>>(Wk, Wkb);
    projT_mma<CD><<<grid_pt, blk, 0, s1>>>(Xd, Wkb, bk, Kt, 1.0f);
    cudaEventRecord(evK, s1);

    // Branch s2: Wv cvt, V projection (natural output); needs Xd from s1
    cvt_bf16_kernel<<<CO * CD / 1024, 256, 0, s2>>>(Wv, Wvb);
    cudaStreamWaitEvent(s2, evXd, 0);
    projN_mma<CD><<<grid_pt, blk, 0, s2>>>(Xd, Wvb, bv, Vr);
    cudaEventRecord(evV, s2);

    // Spine: x_s2 cvt, Wq cvt, Q projection (transposed, scale folded)
    cvt_bf16_kernel<<<(unsigned)((size_t)BB * CS * NN / 1024), 256>>>(x_s2, Xs);
    cvt_bf16_kernel<<<CO * CS / 1024, 256>>>(Wq, Wqb);
    projT_mma<CS><<<grid_pt, blk>>>(Xs, Wqb, bq, Qt, SCALE);

    // Join K before s_mma (emits E + row-sum partials)
    cudaStreamWaitEvent(0, evK, 0);
    s_mma_d<<<dim3(NN / 128, NN / 128, BB), blk>>>(Kt, Qt, Ep, Rpp);

    rp_reduce_kernel<<<dim3(NN / 256, BB), blk>>>(Rpp, Rsum);

    // Join V before vscale
    cudaStreamWaitEvent(0, evV, 0);
    vscale_kernel<<<(unsigned)((size_t)BB * CO * NN / 2048), 256>>>(Vr, Rsum, Vb);

    out_mma_d<<<dim3(NN / 128, CO / 128, BB), blk, O_SMEM>>>(Vb, Ep, x_s2, out);
}